// round 1
// baseline (speedup 1.0000x reference)
#include <cuda_runtime.h>
#include <math.h>

#define NGENES 512
#define NB0 32
#define NB1 64
#define NB2 128
#define OFF0 0
#define OFF1 (NGENES * NB0)            /* 16384  */
#define OFF2 (OFF1 + NGENES * NB1)     /* 49152  */
#define HTOT (OFF2 + NGENES * NB2)     /* 114688 */

// L2-resident scratch (no allocations allowed -> __device__ globals)
__device__ int   g_hist[HTOT];
__device__ float g_logits[HTOT];

// Exact integer reproduction of jnp.searchsorted(interior_bins, x, side='left')
// for equal-width bins over [0, 20000): idx = ceil(x/bw) - 1 clamped at 0.
// (x*nb - 1)/20000 with C++ trunc-toward-zero handles x==0 correctly (-1/20000 == 0).
__device__ __forceinline__ int bin_idx(int x, int nb) {
    return (x * nb - 1) / 20000;
}

__global__ void zero_hist_kernel() {
    int i = blockIdx.x * blockDim.x + threadIdx.x;
    if (i < HTOT) g_hist[i] = 0;
}

__device__ __forceinline__ void hist_one(int x, int g) {
    atomicAdd(&g_hist[OFF0 + g * NB0 + bin_idx(x, NB0)], 1);
    atomicAdd(&g_hist[OFF1 + g * NB1 + bin_idx(x, NB1)], 1);
    atomicAdd(&g_hist[OFF2 + g * NB2 + bin_idx(x, NB2)], 1);
}

__global__ void hist_kernel(const int* __restrict__ pos,
                            const int* __restrict__ gene, int n) {
    int i = (blockIdx.x * blockDim.x + threadIdx.x) * 4;
    if (i + 3 < n) {
        int4 p = *reinterpret_cast<const int4*>(pos + i);
        int4 g = *reinterpret_cast<const int4*>(gene + i);
        hist_one(p.x, g.x);
        hist_one(p.y, g.y);
        hist_one(p.z, g.z);
        hist_one(p.w, g.w);
    } else {
        for (; i < n; i++) hist_one(pos[i], gene[i]);
    }
}

// One block per (gene, binset). 128 threads; thread t owns bin t (t < nb).
__global__ void mlp_softmax_kernel(const float* __restrict__ W1,
                                   const float* __restrict__ B1,
                                   const float* __restrict__ W2,
                                   const float* __restrict__ B2) {
    int gene = blockIdx.x;
    int k    = blockIdx.y;
    int nb   = (k == 0) ? NB0 : (k == 1) ? NB1 : NB2;
    int off  = (k == 0) ? OFF0 : (k == 1) ? OFF1 : OFF2;
    float inv_bw = (float)nb / 20000.0f;

    __shared__ float w1[32], b1[32], w2[32];
    __shared__ float red[128];
    int t = threadIdx.x;
    if (t < 32) {
        w1[t] = W1[k * 32 + t];
        b1[t] = B1[k * 32 + t];
        w2[t] = W2[k * 32 + t];
    }
    __syncthreads();

    float h = -INFINITY;
    if (t < nb) {
        float c = (float)g_hist[off + gene * nb + t] * inv_bw;
        float acc = B2[k];
#pragma unroll
        for (int j = 0; j < 32; j++)
            acc += fmaxf(fmaf(c, w1[j], b1[j]), 0.0f) * w2[j];
        h = acc;
    }

    // block max
    red[t] = h;
    __syncthreads();
    for (int s = 64; s > 0; s >>= 1) {
        if (t < s) red[t] = fmaxf(red[t], red[t + s]);
        __syncthreads();
    }
    float m = red[0];
    __syncthreads();

    // block sum of exp
    float e = (t < nb) ? __expf(h - m) : 0.0f;
    red[t] = e;
    __syncthreads();
    for (int s = 64; s > 0; s >>= 1) {
        if (t < s) red[t] += red[t + s];
        __syncthreads();
    }
    float lse = logf(red[0]);

    if (t < nb) g_logits[off + gene * nb + t] = h - m - lse;
}

__global__ void frag_kernel(const int* __restrict__ coords,
                            const int* __restrict__ gene,
                            float* __restrict__ out, int n, float cconst) {
    int i = (blockIdx.x * blockDim.x + threadIdx.x) * 4;
    if (i + 3 < n) {
        int4 x = *reinterpret_cast<const int4*>(coords + i);
        int4 g = *reinterpret_cast<const int4*>(gene + i);
        float4 r;
        r.x = cconst + g_logits[OFF0 + g.x * NB0 + bin_idx(x.x, NB0)]
                     + g_logits[OFF1 + g.x * NB1 + bin_idx(x.x, NB1)]
                     + g_logits[OFF2 + g.x * NB2 + bin_idx(x.x, NB2)];
        r.y = cconst + g_logits[OFF0 + g.y * NB0 + bin_idx(x.y, NB0)]
                     + g_logits[OFF1 + g.y * NB1 + bin_idx(x.y, NB1)]
                     + g_logits[OFF2 + g.y * NB2 + bin_idx(x.y, NB2)];
        r.z = cconst + g_logits[OFF0 + g.z * NB0 + bin_idx(x.z, NB0)]
                     + g_logits[OFF1 + g.z * NB1 + bin_idx(x.z, NB1)]
                     + g_logits[OFF2 + g.z * NB2 + bin_idx(x.z, NB2)];
        r.w = cconst + g_logits[OFF0 + g.w * NB0 + bin_idx(x.w, NB0)]
                     + g_logits[OFF1 + g.w * NB1 + bin_idx(x.w, NB1)]
                     + g_logits[OFF2 + g.w * NB2 + bin_idx(x.w, NB2)];
        *reinterpret_cast<float4*>(out + i) = r;
    } else {
        for (; i < n; i++) {
            int x = coords[i], g = gene[i];
            out[i] = cconst + g_logits[OFF0 + g * NB0 + bin_idx(x, NB0)]
                            + g_logits[OFF1 + g * NB1 + bin_idx(x, NB1)]
                            + g_logits[OFF2 + g * NB2 + bin_idx(x, NB2)];
        }
    }
}

extern "C" void kernel_launch(void* const* d_in, const int* in_sizes, int n_in,
                              void* d_out, int out_size) {
    const int*   coords = (const int*)d_in[0];   // coordinates       [2M]
    const int*   fgene  = (const int*)d_in[1];   // frag_local_gene_ix [2M]
    const int*   mpos   = (const int*)d_in[2];   // motif_positions   [5M]
    const int*   mgene  = (const int*)d_in[3];   // motif_local_gene_ix [5M]
    // d_in[4..6] = bins0/1/2 (unused: equal-width bins computed in closed form)
    const float* W1 = (const float*)d_in[7];     // (3,1,32)
    const float* B1 = (const float*)d_in[8];     // (3,32)
    const float* W2 = (const float*)d_in[9];     // (3,32,1)
    const float* B2 = (const float*)d_in[10];    // (3,1)

    int nfrag = in_sizes[0];
    int nmot  = in_sizes[2];
    float* out = (float*)d_out;

    // log(32) + log(64) + log(128) - log(20000)
    const float cconst = logf(262144.0f / 20000.0f);

    zero_hist_kernel<<<(HTOT + 255) / 256, 256>>>();
    hist_kernel<<<(nmot + 1023) / 1024, 256>>>(mpos, mgene, nmot);
    mlp_softmax_kernel<<<dim3(NGENES, 3), 128>>>(W1, B1, W2, B2);
    frag_kernel<<<(nfrag + 1023) / 1024, 256>>>(coords, fgene, out, nfrag, cconst);
}

// round 2
// speedup vs baseline: 2.4825x; 2.4825x over previous
#include <cuda_runtime.h>
#include <math.h>

#define NGENES 512
#define NBF 128                         /* fine bins */
#define HTOT (NGENES * NBF)             /* 65536 */

// L2-resident scratch (no allocations allowed -> __device__ globals)
__device__ int   g_hist[HTOT];          // fine (128-bin) histogram per gene
__device__ float g_comb[HTOT];          // combined logits table: L0+L1+L2

// Exact integer reproduction of jnp.searchsorted(interior_bins, x, side='left')
// for equal-width bins: idx = ceil(x*nb/20000) - 1, clamped at 0 via trunc division.
__device__ __forceinline__ int bin_idx128(int x) {
    return (x * NBF - 1) / 20000;
}

__global__ void zero_hist_kernel() {
    int i = blockIdx.x * blockDim.x + threadIdx.x;
    if (i < HTOT) g_hist[i] = 0;
}

// One atomic per motif: fine 128-bin histogram only.
__global__ void hist_kernel(const int* __restrict__ pos,
                            const int* __restrict__ gene, int n) {
    int i = (blockIdx.x * blockDim.x + threadIdx.x) * 4;
    if (i + 3 < n) {
        int4 p = *reinterpret_cast<const int4*>(pos + i);
        int4 g = *reinterpret_cast<const int4*>(gene + i);
        atomicAdd(&g_hist[g.x * NBF + bin_idx128(p.x)], 1);
        atomicAdd(&g_hist[g.y * NBF + bin_idx128(p.y)], 1);
        atomicAdd(&g_hist[g.z * NBF + bin_idx128(p.z)], 1);
        atomicAdd(&g_hist[g.w * NBF + bin_idx128(p.w)], 1);
    } else {
        for (; i < n; i++)
            atomicAdd(&g_hist[gene[i] * NBF + bin_idx128(pos[i])], 1);
    }
}

// One block per gene, 128 threads. Derives coarse counts from fine hist,
// runs the 1->32->1 MLP per bin for each binset, softmax per binset,
// and writes the COMBINED logits table g_comb[g*128 + t] = l0[t>>2]+l1[t>>1]+l2[t].
__global__ void mlp_softmax_kernel(const float* __restrict__ W1,
                                   const float* __restrict__ B1,
                                   const float* __restrict__ W2,
                                   const float* __restrict__ B2) {
    int gene = blockIdx.x;
    int t = threadIdx.x;

    __shared__ int   cfine[NBF];
    __shared__ float w1[3][32], b1[3][32], w2[3][32];
    __shared__ float red[128];
    __shared__ float l0[32], l1[64], scal[8];

    cfine[t] = g_hist[gene * NBF + t];
    if (t < 96) {
        int k = t >> 5, j = t & 31;
        w1[k][j] = W1[t];
        b1[k][j] = B1[t];
        w2[k][j] = W2[t];
    }
    __syncthreads();

    // process binsets k = 0 (nb=32), 1 (nb=64), 2 (nb=128)
    float l2_mine = 0.0f;   // binset-2 logit owned by thread t
    for (int k = 0; k < 3; k++) {
        int nb = 32 << k;
        float inv_bw = (float)nb / 20000.0f;

        float h = -INFINITY;
        if (t < nb) {
            int cnt;
            if (k == 2)      cnt = cfine[t];
            else if (k == 1) cnt = cfine[2 * t] + cfine[2 * t + 1];
            else             cnt = cfine[4 * t] + cfine[4 * t + 1]
                                 + cfine[4 * t + 2] + cfine[4 * t + 3];
            float c = (float)cnt * inv_bw;
            float acc = B2[k];
#pragma unroll
            for (int j = 0; j < 32; j++)
                acc += fmaxf(fmaf(c, w1[k][j], b1[k][j]), 0.0f) * w2[k][j];
            h = acc;
        }

        // block max
        red[t] = h;
        __syncthreads();
        for (int s = 64; s > 0; s >>= 1) {
            if (t < s) red[t] = fmaxf(red[t], red[t + s]);
            __syncthreads();
        }
        float m = red[0];
        __syncthreads();
        // block sum of exp
        red[t] = (t < nb) ? __expf(h - m) : 0.0f;
        __syncthreads();
        for (int s = 64; s > 0; s >>= 1) {
            if (t < s) red[t] += red[t + s];
            __syncthreads();
        }
        float lse = m + logf(red[0]);
        __syncthreads();

        if (t < nb) {
            float lg = h - lse;
            if (k == 0) l0[t] = lg;
            else if (k == 1) l1[t] = lg;
            else l2_mine = lg;
        }
        __syncthreads();
    }

    g_comb[gene * NBF + t] = l0[t >> 2] + l1[t >> 1] + l2_mine;
}

// One gather per fragment from the combined table.
__global__ void frag_kernel(const int* __restrict__ coords,
                            const int* __restrict__ gene,
                            float* __restrict__ out, int n, float cconst) {
    int i = (blockIdx.x * blockDim.x + threadIdx.x) * 4;
    if (i + 3 < n) {
        int4 x = *reinterpret_cast<const int4*>(coords + i);
        int4 g = *reinterpret_cast<const int4*>(gene + i);
        float4 r;
        r.x = cconst + g_comb[g.x * NBF + bin_idx128(x.x)];
        r.y = cconst + g_comb[g.y * NBF + bin_idx128(x.y)];
        r.z = cconst + g_comb[g.z * NBF + bin_idx128(x.z)];
        r.w = cconst + g_comb[g.w * NBF + bin_idx128(x.w)];
        *reinterpret_cast<float4*>(out + i) = r;
    } else {
        for (; i < n; i++)
            out[i] = cconst + g_comb[gene[i] * NBF + bin_idx128(coords[i])];
    }
}

extern "C" void kernel_launch(void* const* d_in, const int* in_sizes, int n_in,
                              void* d_out, int out_size) {
    const int*   coords = (const int*)d_in[0];   // coordinates        [2M]
    const int*   fgene  = (const int*)d_in[1];   // frag_local_gene_ix [2M]
    const int*   mpos   = (const int*)d_in[2];   // motif_positions    [5M]
    const int*   mgene  = (const int*)d_in[3];   // motif_local_gene_ix[5M]
    // d_in[4..6] = bins0/1/2 (unused: equal-width bins computed in closed form)
    const float* W1 = (const float*)d_in[7];     // (3,1,32)
    const float* B1 = (const float*)d_in[8];     // (3,32)
    const float* W2 = (const float*)d_in[9];     // (3,32,1)
    const float* B2 = (const float*)d_in[10];    // (3,1)

    int nfrag = in_sizes[0];
    int nmot  = in_sizes[2];
    float* out = (float*)d_out;

    // log(32) + log(64) + log(128) - log(20000)
    const float cconst = logf(262144.0f / 20000.0f);

    zero_hist_kernel<<<(HTOT + 255) / 256, 256>>>();
    hist_kernel<<<(nmot + 1023) / 1024, 256>>>(mpos, mgene, nmot);
    mlp_softmax_kernel<<<NGENES, NBF>>>(W1, B1, W2, B2);
    frag_kernel<<<(nfrag + 1023) / 1024, 256>>>(coords, fgene, out, nfrag, cconst);
}

// round 3
// speedup vs baseline: 2.5826x; 1.0403x over previous
#include <cuda_runtime.h>
#include <math.h>

#define NGENES 512
#define NBF 128                         /* fine bins */
#define HTOT (NGENES * NBF)             /* 65536 */

// L2-resident scratch (no allocations allowed -> __device__ globals).
// g_hist is zero-initialized at module load and RE-ZEROED by mlp_softmax_kernel
// after reading, so every graph replay starts from a clean histogram.
__device__ int   g_hist[HTOT];          // fine (128-bin) histogram per gene
__device__ float g_comb[HTOT];          // combined logits table: L0+L1+L2

// Exact integer reproduction of jnp.searchsorted(interior_bins, x, side='left')
// for equal-width bins: idx = ceil(x*nb/20000) - 1, clamped at 0 via trunc division.
__device__ __forceinline__ int bin_idx128(int x) {
    return (x * NBF - 1) / 20000;
}

// One atomic (RED.ADD) per motif: fine 128-bin histogram only.
__global__ void hist_kernel(const int* __restrict__ pos,
                            const int* __restrict__ gene, int n) {
    int i = (blockIdx.x * blockDim.x + threadIdx.x) * 4;
    if (i + 3 < n) {
        int4 p = *reinterpret_cast<const int4*>(pos + i);
        int4 g = *reinterpret_cast<const int4*>(gene + i);
        atomicAdd(&g_hist[g.x * NBF + bin_idx128(p.x)], 1);
        atomicAdd(&g_hist[g.y * NBF + bin_idx128(p.y)], 1);
        atomicAdd(&g_hist[g.z * NBF + bin_idx128(p.z)], 1);
        atomicAdd(&g_hist[g.w * NBF + bin_idx128(p.w)], 1);
    } else {
        for (; i < n; i++)
            atomicAdd(&g_hist[gene[i] * NBF + bin_idx128(pos[i])], 1);
    }
}

__device__ __forceinline__ float wmax(float v) {
#pragma unroll
    for (int s = 16; s > 0; s >>= 1) v = fmaxf(v, __shfl_xor_sync(0xffffffffu, v, s));
    return v;
}
__device__ __forceinline__ float wsum(float v) {
#pragma unroll
    for (int s = 16; s > 0; s >>= 1) v += __shfl_xor_sync(0xffffffffu, v, s);
    return v;
}

__device__ __forceinline__ float mlp_eval(float c, const float* __restrict__ w1,
                                          const float* __restrict__ b1,
                                          const float* __restrict__ w2, float b2) {
    float acc = b2;
#pragma unroll
    for (int j = 0; j < 32; j++)
        acc += fmaxf(fmaf(c, w1[j], b1[j]), 0.0f) * w2[j];
    return acc;
}

// Warp-per-gene: lane L owns fine bins [4L, 4L+3]. All reductions are warp
// shuffles; the combined logit for a fine bin is lane-local. Also re-zeroes
// g_hist for the next graph replay.
__global__ void mlp_softmax_kernel(const float* __restrict__ W1,
                                   const float* __restrict__ B1,
                                   const float* __restrict__ W2,
                                   const float* __restrict__ B2) {
    __shared__ float w1[3][32], b1[3][32], w2[3][32];
    int t = threadIdx.x;
    if (t < 96) {
        int k = t >> 5, j = t & 31;
        w1[k][j] = W1[t];
        b1[k][j] = B1[t];
        w2[k][j] = W2[t];
    }
    __syncthreads();

    int warp = t >> 5, lane = t & 31;
    int gene = blockIdx.x * 8 + warp;
    int base = gene * NBF + lane * 4;

    int4 cf = *reinterpret_cast<const int4*>(&g_hist[base]);

    // ---- binset 0 (nb=32): one bin per lane ----
    {
        float c = (float)(cf.x + cf.y + cf.z + cf.w) * (32.0f / 20000.0f);
        float h = mlp_eval(c, w1[0], b1[0], w2[0], B2[0]);
        float m = wmax(h);
        float s = wsum(__expf(h - m));
        float l0 = h - m - logf(s);

        // ---- binset 1 (nb=64): two bins per lane ----
        float ca = (float)(cf.x + cf.y) * (64.0f / 20000.0f);
        float cb = (float)(cf.z + cf.w) * (64.0f / 20000.0f);
        float ha = mlp_eval(ca, w1[1], b1[1], w2[1], B2[1]);
        float hb = mlp_eval(cb, w1[1], b1[1], w2[1], B2[1]);
        float m1 = wmax(fmaxf(ha, hb));
        float s1 = wsum(__expf(ha - m1) + __expf(hb - m1));
        float lse1 = m1 + logf(s1);
        float l1a = ha - lse1, l1b = hb - lse1;

        // ---- binset 2 (nb=128): four bins per lane ----
        const float sc2 = 128.0f / 20000.0f;
        float h0 = mlp_eval((float)cf.x * sc2, w1[2], b1[2], w2[2], B2[2]);
        float h1 = mlp_eval((float)cf.y * sc2, w1[2], b1[2], w2[2], B2[2]);
        float h2 = mlp_eval((float)cf.z * sc2, w1[2], b1[2], w2[2], B2[2]);
        float h3 = mlp_eval((float)cf.w * sc2, w1[2], b1[2], w2[2], B2[2]);
        float m2 = wmax(fmaxf(fmaxf(h0, h1), fmaxf(h2, h3)));
        float s2 = wsum(__expf(h0 - m2) + __expf(h1 - m2) +
                        __expf(h2 - m2) + __expf(h3 - m2));
        float lse2 = m2 + logf(s2);

        float4 r;
        r.x = l0 + l1a + (h0 - lse2);
        r.y = l0 + l1a + (h1 - lse2);
        r.z = l0 + l1b + (h2 - lse2);
        r.w = l0 + l1b + (h3 - lse2);
        *reinterpret_cast<float4*>(&g_comb[base]) = r;
    }

    // re-zero histogram for the next replay
    int4 z = make_int4(0, 0, 0, 0);
    *reinterpret_cast<int4*>(&g_hist[base]) = z;
}

// One gather per fragment from the combined table; 8 fragments per thread.
__global__ void frag_kernel(const int* __restrict__ coords,
                            const int* __restrict__ gene,
                            float* __restrict__ out, int n, float cconst) {
    int i = (blockIdx.x * blockDim.x + threadIdx.x) * 8;
    if (i + 7 < n) {
        int4 x0 = *reinterpret_cast<const int4*>(coords + i);
        int4 x1 = *reinterpret_cast<const int4*>(coords + i + 4);
        int4 g0 = *reinterpret_cast<const int4*>(gene + i);
        int4 g1 = *reinterpret_cast<const int4*>(gene + i + 4);
        float4 r0, r1;
        r0.x = cconst + g_comb[g0.x * NBF + bin_idx128(x0.x)];
        r0.y = cconst + g_comb[g0.y * NBF + bin_idx128(x0.y)];
        r0.z = cconst + g_comb[g0.z * NBF + bin_idx128(x0.z)];
        r0.w = cconst + g_comb[g0.w * NBF + bin_idx128(x0.w)];
        r1.x = cconst + g_comb[g1.x * NBF + bin_idx128(x1.x)];
        r1.y = cconst + g_comb[g1.y * NBF + bin_idx128(x1.y)];
        r1.z = cconst + g_comb[g1.z * NBF + bin_idx128(x1.z)];
        r1.w = cconst + g_comb[g1.w * NBF + bin_idx128(x1.w)];
        *reinterpret_cast<float4*>(out + i) = r0;
        *reinterpret_cast<float4*>(out + i + 4) = r1;
    } else {
        for (; i < n; i++)
            out[i] = cconst + g_comb[gene[i] * NBF + bin_idx128(coords[i])];
    }
}

extern "C" void kernel_launch(void* const* d_in, const int* in_sizes, int n_in,
                              void* d_out, int out_size) {
    const int*   coords = (const int*)d_in[0];   // coordinates        [2M]
    const int*   fgene  = (const int*)d_in[1];   // frag_local_gene_ix [2M]
    const int*   mpos   = (const int*)d_in[2];   // motif_positions    [5M]
    const int*   mgene  = (const int*)d_in[3];   // motif_local_gene_ix[5M]
    // d_in[4..6] = bins0/1/2 (unused: equal-width bins computed in closed form)
    const float* W1 = (const float*)d_in[7];     // (3,1,32)
    const float* B1 = (const float*)d_in[8];     // (3,32)
    const float* W2 = (const float*)d_in[9];     // (3,32,1)
    const float* B2 = (const float*)d_in[10];    // (3,1)

    int nfrag = in_sizes[0];
    int nmot  = in_sizes[2];
    float* out = (float*)d_out;

    // log(32) + log(64) + log(128) - log(20000)
    const float cconst = logf(262144.0f / 20000.0f);

    hist_kernel<<<(nmot + 1023) / 1024, 256>>>(mpos, mgene, nmot);
    mlp_softmax_kernel<<<NGENES / 8, 256>>>(W1, B1, W2, B2);
    frag_kernel<<<(nfrag + 2047) / 2048, 256>>>(coords, fgene, out, nfrag, cconst);
}

// round 4
// speedup vs baseline: 2.8190x; 1.0916x over previous
#include <cuda_runtime.h>
#include <math.h>

#define NGENES 512
#define NBF 128                         /* fine bins */
#define HTOT (NGENES * NBF)             /* 65536 */
#define REPL 4                          /* histogram replicas (L2 slice spread) */
#define MAXFRAG 2100000

// L2-resident scratch (no allocations allowed -> __device__ globals).
// g_hist is zero-initialized at module load and RE-ZEROED by mlp_softmax_kernel
// after reading, so every graph replay starts from a clean histogram.
__device__ int            g_hist[REPL][HTOT];
__device__ float          g_comb[HTOT];       // combined logits: L0+L1+L2
__device__ unsigned short g_fkey[MAXFRAG];    // per-fragment packed key g*128+bin

// Exact integer reproduction of jnp.searchsorted(interior_bins, x, side='left')
// for equal-width bins: idx = ceil(x*nb/20000) - 1, clamped at 0 via trunc division.
__device__ __forceinline__ int bin_idx128(int x) {
    return (x * NBF - 1) / 20000;
}

// Fused kernel: "hist blocks" do one RED.ADD per motif into replica (b&3);
// "key blocks" (interleaved 2-of-7) precompute packed fragment keys, riding
// the idle DRAM/ALU pipes while the atomic phase clogs the LTS atomic ALU.
__global__ void hist_and_key_kernel(const int* __restrict__ mpos,
                                    const int* __restrict__ mgene, int nmot,
                                    const int* __restrict__ coords,
                                    const int* __restrict__ fgene, int nfrag) {
    int b  = blockIdx.x;
    int r7 = b % 7, q = b / 7;

    if (r7 < 2) {
        // ---- fragment key block ----
        int kb = q * 2 + r7;
        int i  = kb * 2048 + threadIdx.x * 8;
        if (i + 7 < nfrag) {
            int4 x0 = *reinterpret_cast<const int4*>(coords + i);
            int4 x1 = *reinterpret_cast<const int4*>(coords + i + 4);
            int4 g0 = *reinterpret_cast<const int4*>(fgene + i);
            int4 g1 = *reinterpret_cast<const int4*>(fgene + i + 4);
            unsigned int k0 = (unsigned)(g0.x * NBF + bin_idx128(x0.x));
            unsigned int k1 = (unsigned)(g0.y * NBF + bin_idx128(x0.y));
            unsigned int k2 = (unsigned)(g0.z * NBF + bin_idx128(x0.z));
            unsigned int k3 = (unsigned)(g0.w * NBF + bin_idx128(x0.w));
            unsigned int k4 = (unsigned)(g1.x * NBF + bin_idx128(x1.x));
            unsigned int k5 = (unsigned)(g1.y * NBF + bin_idx128(x1.y));
            unsigned int k6 = (unsigned)(g1.z * NBF + bin_idx128(x1.z));
            unsigned int k7 = (unsigned)(g1.w * NBF + bin_idx128(x1.w));
            uint4 pk;
            pk.x = k0 | (k1 << 16);
            pk.y = k2 | (k3 << 16);
            pk.z = k4 | (k5 << 16);
            pk.w = k6 | (k7 << 16);
            *reinterpret_cast<uint4*>(g_fkey + i) = pk;
        } else if (i < nfrag) {
            for (; i < nfrag; i++)
                g_fkey[i] = (unsigned short)(fgene[i] * NBF + bin_idx128(coords[i]));
        }
    } else {
        // ---- histogram block ----
        int hb = q * 5 + (r7 - 2);
        int i  = hb * 2048 + threadIdx.x * 8;
        int* __restrict__ hist = g_hist[b & 3];
        if (i + 7 < nmot) {
            int4 p0 = *reinterpret_cast<const int4*>(mpos + i);
            int4 p1 = *reinterpret_cast<const int4*>(mpos + i + 4);
            int4 g0 = *reinterpret_cast<const int4*>(mgene + i);
            int4 g1 = *reinterpret_cast<const int4*>(mgene + i + 4);
            atomicAdd(&hist[g0.x * NBF + bin_idx128(p0.x)], 1);
            atomicAdd(&hist[g0.y * NBF + bin_idx128(p0.y)], 1);
            atomicAdd(&hist[g0.z * NBF + bin_idx128(p0.z)], 1);
            atomicAdd(&hist[g0.w * NBF + bin_idx128(p0.w)], 1);
            atomicAdd(&hist[g1.x * NBF + bin_idx128(p1.x)], 1);
            atomicAdd(&hist[g1.y * NBF + bin_idx128(p1.y)], 1);
            atomicAdd(&hist[g1.z * NBF + bin_idx128(p1.z)], 1);
            atomicAdd(&hist[g1.w * NBF + bin_idx128(p1.w)], 1);
        } else if (i < nmot) {
            for (; i < nmot; i++)
                atomicAdd(&hist[mgene[i] * NBF + bin_idx128(mpos[i])], 1);
        }
    }
}

__device__ __forceinline__ float wmax(float v) {
#pragma unroll
    for (int s = 16; s > 0; s >>= 1) v = fmaxf(v, __shfl_xor_sync(0xffffffffu, v, s));
    return v;
}
__device__ __forceinline__ float wsum(float v) {
#pragma unroll
    for (int s = 16; s > 0; s >>= 1) v += __shfl_xor_sync(0xffffffffu, v, s);
    return v;
}

__device__ __forceinline__ float mlp_eval(float c, const float* __restrict__ w1,
                                          const float* __restrict__ b1,
                                          const float* __restrict__ w2, float b2) {
    float acc = b2;
#pragma unroll
    for (int j = 0; j < 32; j++)
        acc += fmaxf(fmaf(c, w1[j], b1[j]), 0.0f) * w2[j];
    return acc;
}

// Warp-per-gene: lane L owns fine bins [4L, 4L+3]. Sums the histogram
// replicas, runs MLP+softmax for all 3 binsets with warp shuffles only,
// writes combined logits, and re-zeroes g_hist for the next graph replay.
__global__ void mlp_softmax_kernel(const float* __restrict__ W1,
                                   const float* __restrict__ B1,
                                   const float* __restrict__ W2,
                                   const float* __restrict__ B2) {
    __shared__ float w1[3][32], b1[3][32], w2[3][32];
    int t = threadIdx.x;
    if (t < 96) {
        int k = t >> 5, j = t & 31;
        w1[k][j] = W1[t];
        b1[k][j] = B1[t];
        w2[k][j] = W2[t];
    }
    __syncthreads();

    int warp = t >> 5, lane = t & 31;
    int gene = blockIdx.x * 8 + warp;
    int base = gene * NBF + lane * 4;

    int4 cf = make_int4(0, 0, 0, 0);
#pragma unroll
    for (int r = 0; r < REPL; r++) {
        int4 c = *reinterpret_cast<const int4*>(&g_hist[r][base]);
        cf.x += c.x; cf.y += c.y; cf.z += c.z; cf.w += c.w;
        *reinterpret_cast<int4*>(&g_hist[r][base]) = make_int4(0, 0, 0, 0);
    }

    // ---- binset 0 (nb=32): one bin per lane ----
    float c0 = (float)(cf.x + cf.y + cf.z + cf.w) * (32.0f / 20000.0f);
    float h = mlp_eval(c0, w1[0], b1[0], w2[0], B2[0]);
    float m = wmax(h);
    float s = wsum(__expf(h - m));
    float l0 = h - m - logf(s);

    // ---- binset 1 (nb=64): two bins per lane ----
    float ca = (float)(cf.x + cf.y) * (64.0f / 20000.0f);
    float cb = (float)(cf.z + cf.w) * (64.0f / 20000.0f);
    float ha = mlp_eval(ca, w1[1], b1[1], w2[1], B2[1]);
    float hb = mlp_eval(cb, w1[1], b1[1], w2[1], B2[1]);
    float m1 = wmax(fmaxf(ha, hb));
    float s1 = wsum(__expf(ha - m1) + __expf(hb - m1));
    float lse1 = m1 + logf(s1);
    float l1a = ha - lse1, l1b = hb - lse1;

    // ---- binset 2 (nb=128): four bins per lane ----
    const float sc2 = 128.0f / 20000.0f;
    float h0 = mlp_eval((float)cf.x * sc2, w1[2], b1[2], w2[2], B2[2]);
    float h1 = mlp_eval((float)cf.y * sc2, w1[2], b1[2], w2[2], B2[2]);
    float h2 = mlp_eval((float)cf.z * sc2, w1[2], b1[2], w2[2], B2[2]);
    float h3 = mlp_eval((float)cf.w * sc2, w1[2], b1[2], w2[2], B2[2]);
    float m2 = wmax(fmaxf(fmaxf(h0, h1), fmaxf(h2, h3)));
    float s2 = wsum(__expf(h0 - m2) + __expf(h1 - m2) +
                    __expf(h2 - m2) + __expf(h3 - m2));
    float lse2 = m2 + logf(s2);

    float4 r;
    r.x = l0 + l1a + (h0 - lse2);
    r.y = l0 + l1a + (h1 - lse2);
    r.z = l0 + l1b + (h2 - lse2);
    r.w = l0 + l1b + (h3 - lse2);
    *reinterpret_cast<float4*>(&g_comb[base]) = r;
}

// Final gather: 8 fragments per thread from packed u16 keys.
__global__ void frag_kernel(float* __restrict__ out, int n, float cconst) {
    int i = (blockIdx.x * blockDim.x + threadIdx.x) * 8;
    if (i + 7 < n) {
        uint4 pk = *reinterpret_cast<const uint4*>(g_fkey + i);
        float4 r0, r1;
        r0.x = cconst + g_comb[pk.x & 0xffffu];
        r0.y = cconst + g_comb[pk.x >> 16];
        r0.z = cconst + g_comb[pk.y & 0xffffu];
        r0.w = cconst + g_comb[pk.y >> 16];
        r1.x = cconst + g_comb[pk.z & 0xffffu];
        r1.y = cconst + g_comb[pk.z >> 16];
        r1.z = cconst + g_comb[pk.w & 0xffffu];
        r1.w = cconst + g_comb[pk.w >> 16];
        *reinterpret_cast<float4*>(out + i) = r0;
        *reinterpret_cast<float4*>(out + i + 4) = r1;
    } else {
        for (; i < n; i++)
            out[i] = cconst + g_comb[g_fkey[i]];
    }
}

extern "C" void kernel_launch(void* const* d_in, const int* in_sizes, int n_in,
                              void* d_out, int out_size) {
    const int*   coords = (const int*)d_in[0];   // coordinates        [2M]
    const int*   fgene  = (const int*)d_in[1];   // frag_local_gene_ix [2M]
    const int*   mpos   = (const int*)d_in[2];   // motif_positions    [5M]
    const int*   mgene  = (const int*)d_in[3];   // motif_local_gene_ix[5M]
    // d_in[4..6] = bins0/1/2 (unused: equal-width bins computed in closed form)
    const float* W1 = (const float*)d_in[7];     // (3,1,32)
    const float* B1 = (const float*)d_in[8];     // (3,32)
    const float* W2 = (const float*)d_in[9];     // (3,32,1)
    const float* B2 = (const float*)d_in[10];    // (3,1)

    int nfrag = in_sizes[0];
    int nmot  = in_sizes[2];
    float* out = (float*)d_out;

    // log(32) + log(64) + log(128) - log(20000)
    const float cconst = logf(262144.0f / 20000.0f);

    int nhb = (nmot + 2047) / 2048;   // hist blocks (8 motifs/thread, 256 thr)
    int nkb = (nfrag + 2047) / 2048;  // key blocks
    int q   = (nhb + 4) / 5;
    int q2  = (nkb + 1) / 2;
    if (q2 > q) q = q2;
    int grid = 7 * q;

    hist_and_key_kernel<<<grid, 256>>>(mpos, mgene, nmot, coords, fgene, nfrag);
    mlp_softmax_kernel<<<NGENES / 8, 256>>>(W1, B1, W2, B2);
    frag_kernel<<<(nfrag + 2047) / 2048, 256>>>(out, nfrag, cconst);
}